// round 9
// baseline (speedup 1.0000x reference)
#include <cuda_runtime.h>
#include <math_constants.h>
#include <cstdint>

// Problem constants
#define BB 4
#define LL 8192
#define DD 768
#define MAXS 100
#define GM (BB*MAXS)   // 400
#define M2 512         // padded M storage (rows 400-511 zero)
#define GN DD          // 768
#define GK DD          // 768
#define NK8 (GK/8)     // 96
#define MTC 28         // computed m-tiles (448 rows >= 400)
#define NT (GN/8)      // 96 n-tiles

// pool config
#define TCH 32
#define PBLK 192
#define POOL_BLOCKS ((LL/TCH)*BB)        // 1024

// gemm config
#define SPLITK 6
#define K8_PER_Z (NK8/SPLITK)   // 16 stages per block
#define GEMM_THREADS 128

// Scratch (device globals; allocation is forbidden)
__device__ float g_pooled[M2 * GK];            // [512][768] pooled, m-major
__device__ float4 g_afb[NK8 * MTC * 32];       // A frags big   [k8][mt][t]
__device__ float4 g_afs[NK8 * MTC * 32];       // A frags small
__device__ float2 g_bfb[NK8 * NT * 32];        // B frags big   [k8][nt][t]
__device__ float2 g_bfs[NK8 * NT * 32];        // B frags small
__device__ float g_part[SPLITK][M2 * GN];      // split-K partials

#define A_POS (NK8 * MTC * 32)   // 86016
#define B_POS (NK8 * NT * 32)    // 294912

// ---------------------------------------------------------------------------
// helpers
// ---------------------------------------------------------------------------
__device__ __forceinline__ void atomMaxF(float* a, float v) {
    if (v >= 0.0f) atomicMax((int*)a, __float_as_int(v));
    else           atomicMin((unsigned int*)a, __float_as_uint(v));
}
__device__ __forceinline__ void cp_async16(unsigned int smem, const void* gmem) {
    asm volatile("cp.async.cg.shared.global [%0], [%1], 16;\n" :: "r"(smem), "l"(gmem));
}
__device__ __forceinline__ void cp_commit() {
    asm volatile("cp.async.commit_group;\n");
}
template <int N>
__device__ __forceinline__ void cp_wait() {
    asm volatile("cp.async.wait_group %0;\n" :: "n"(N));
}
__device__ __forceinline__ float to_tf32(float x) {
    unsigned u;
    asm("cvt.rna.tf32.f32 %0, %1;" : "=r"(u) : "f"(x));
    return __uint_as_float(u);
}
__device__ __forceinline__ void tf32_split(float x, float& big, float& small) {
    big = to_tf32(x);
    float r = isinf(x) ? 0.0f : x - big;
    small = to_tf32(r);
}
__device__ __forceinline__ void mma_tf32(float4& d, uint4 a, float2 b) {
    asm("mma.sync.aligned.m16n8k8.row.col.f32.tf32.tf32.f32 "
        "{%0,%1,%2,%3}, {%4,%5,%6,%7}, {%8,%9}, {%0,%1,%2,%3};"
        : "+f"(d.x), "+f"(d.y), "+f"(d.z), "+f"(d.w)
        : "r"(a.x), "r"(a.y), "r"(a.z), "r"(a.w),
          "r"(__float_as_uint(b.x)), "r"(__float_as_uint(b.y)));
}

// ---------------------------------------------------------------------------
// Init: g_pooled rows <400: -inf on valid slots else 0; rows 400-511: 0.
// ---------------------------------------------------------------------------
__global__ __launch_bounds__(256) void init_kernel(const int* __restrict__ ids) {
    int i4 = blockIdx.x * 256 + threadIdx.x;       // 0..98303
    int m = (i4 * 4) / DD;
    float val = 0.0f;
    if (m < GM) {
        int b = m / MAXS;
        int s = m - b * MAXS;
        int bbmax = __ldg(&ids[b * LL + LL - 1]);
        val = (s < bbmax) ? -CUDART_INF_F : 0.0f;
    }
    ((float4*)g_pooled)[i4] = make_float4(val, val, val, val);
}

// ---------------------------------------------------------------------------
// Pool: token-parallel segment max into g_pooled[m][d].
// ---------------------------------------------------------------------------
__global__ __launch_bounds__(PBLK) void pool_kernel(const float* __restrict__ wf,
                                                    const int* __restrict__ ids) {
    __shared__ int sid[TCH];
    const int pb = blockIdx.x;
    const int b = pb >> 8;
    const int c0 = (pb & 255) * TCH;
    const int tid = threadIdx.x;
    if (tid < TCH) sid[tid] = ids[b * LL + c0 + tid];
    __syncthreads();

    const float4* __restrict__ base =
        (const float4*)(wf + ((size_t)b * LL + c0) * DD) + tid;

    float4 run = make_float4(-CUDART_INF_F, -CUDART_INF_F, -CUDART_INF_F, -CUDART_INF_F);
    int cur = -1;
    const int d0 = tid * 4;

#pragma unroll
    for (int t0 = 0; t0 < TCH; t0 += 8) {
        float4 v[8];
#pragma unroll
        for (int j = 0; j < 8; ++j)
            v[j] = __ldcs(base + (size_t)(t0 + j) * (DD / 4));
#pragma unroll
        for (int j = 0; j < 8; ++j) {
            int id = sid[t0 + j];
            if (id != cur) {
                if (cur > 0) {
                    float* p = g_pooled + (size_t)(b * MAXS + cur - 1) * DD + d0;
                    atomMaxF(p + 0, run.x);
                    atomMaxF(p + 1, run.y);
                    atomMaxF(p + 2, run.z);
                    atomMaxF(p + 3, run.w);
                }
                cur = id;
                run = make_float4(-CUDART_INF_F, -CUDART_INF_F, -CUDART_INF_F, -CUDART_INF_F);
            }
            if (id > 0) {
                run.x = fmaxf(run.x, v[j].x);
                run.y = fmaxf(run.y, v[j].y);
                run.z = fmaxf(run.z, v[j].z);
                run.w = fmaxf(run.w, v[j].w);
            }
        }
    }
    if (cur > 0) {
        float* p = g_pooled + (size_t)(b * MAXS + cur - 1) * DD + d0;
        atomMaxF(p + 0, run.x);
        atomMaxF(p + 1, run.y);
        atomMaxF(p + 2, run.z);
        atomMaxF(p + 3, run.w);
    }
}

// ---------------------------------------------------------------------------
// Convert: tf32 big/small split into mma fragment order.
// A frag (a0..a3): (g,c) (g+8,c) (g,c+4) (g+8,c+4);  g=t/4, c=t%4
// B frag (b0,b1):  (k=c, n=g) (k=c+4, n=g)
// ---------------------------------------------------------------------------
__global__ __launch_bounds__(256) void convert_kernel(const float* __restrict__ W2) {
    int i = blockIdx.x * 256 + threadIdx.x;
    if (i < A_POS) {
        int t  = i & 31;
        int rest = i >> 5;
        int mt = rest % MTC;
        int k8 = rest / MTC;
        int g = t >> 2, c = t & 3;
        int r0 = mt * 16 + g, r1 = r0 + 8;
        int k0 = k8 * 8 + c,  k1 = k0 + 4;
        float e0 = g_pooled[r0 * GK + k0];
        float e1 = g_pooled[r1 * GK + k0];
        float e2 = g_pooled[r0 * GK + k1];
        float e3 = g_pooled[r1 * GK + k1];
        float4 bgv, smv;
        tf32_split(e0, bgv.x, smv.x);
        tf32_split(e1, bgv.y, smv.y);
        tf32_split(e2, bgv.z, smv.z);
        tf32_split(e3, bgv.w, smv.w);
        // store with [k8][mt][t] layout, mt stride MTC
        int idx = (k8 * MTC + mt) * 32 + t;
        g_afb[idx] = bgv;
        g_afs[idx] = smv;
    } else {
        int j = i - A_POS;
        if (j >= B_POS) return;
        int t  = j & 31;
        int nt = (j >> 5) % NT;
        int k8 = j / (NT * 32);
        int g = t >> 2, c = t & 3;
        int n  = nt * 8 + g;
        int k0 = k8 * 8 + c, k1 = k0 + 4;
        float e0 = W2[(size_t)n * GK + k0];
        float e1 = W2[(size_t)n * GK + k1];
        float2 bgv, smv;
        tf32_split(e0, bgv.x, smv.x);
        tf32_split(e1, bgv.y, smv.y);
        g_bfb[j] = bgv;
        g_bfs[j] = smv;
    }
}

// ---------------------------------------------------------------------------
// GEMM (3xTF32): grid (7, 12, 6) = 504 blocks, 128 thr = 4 warps (2m x 2n).
// Block tile 64m x 64n; warp tile 32m x 32n (2 mt x 4 nt).
// 4-deep cp.async pipeline, wait_group<2>, one barrier per k8 stage.
// ---------------------------------------------------------------------------
__global__ __launch_bounds__(GEMM_THREADS) void gemm_kernel() {
    __shared__ float4 sA[4][2][128];   // [buf][big/sm][mt_local*32+t] 16KB
    __shared__ float2 sB[4][2][256];   // [buf][big/sm][nt_local*32+t] 16KB

    const int mb4 = blockIdx.x * 4;        // mtile base (0..24)
    const int nb8 = blockIdx.y * 8;        // ntile base
    const int z = blockIdx.z;
    const int k8z = z * K8_PER_Z;

    const int tid = threadIdx.x;
    const int lane = tid & 31;
    const int wid = tid >> 5;
    const int mwarp = wid >> 1;            // 0..1
    const int nwarp = wid & 1;             // 0..1

    auto load_stage = [&](int st) {
        if (st < K8_PER_Z) {
            const int buf = st & 3;
            const int k8g = k8z + st;
            const float4* srcAb = g_afb + ((size_t)k8g * MTC + mb4) * 32;
            const float4* srcAs = g_afs + ((size_t)k8g * MTC + mb4) * 32;
            const float4* srcBb = (const float4*)(g_bfb + ((size_t)k8g * NT + nb8) * 32);
            const float4* srcBs = (const float4*)(g_bfs + ((size_t)k8g * NT + nb8) * 32);
            cp_async16((unsigned int)__cvta_generic_to_shared(&sA[buf][0][tid]), srcAb + tid);
            cp_async16((unsigned int)__cvta_generic_to_shared(&sA[buf][1][tid]), srcAs + tid);
            cp_async16((unsigned int)__cvta_generic_to_shared(&sB[buf][0][2 * tid]), srcBb + tid);
            cp_async16((unsigned int)__cvta_generic_to_shared(&sB[buf][1][2 * tid]), srcBs + tid);
        }
        cp_commit();   // empty commit past the end keeps wait<2> bookkeeping exact
    };

    float4 acc[2][4];
#pragma unroll
    for (int i = 0; i < 2; ++i)
#pragma unroll
        for (int j = 0; j < 4; ++j) acc[i][j] = make_float4(0.f, 0.f, 0.f, 0.f);

    load_stage(0);
    load_stage(1);
    load_stage(2);

    for (int st = 0; st < K8_PER_Z; ++st) {
        cp_wait<2>();
        __syncthreads();        // stage st resident; all warps done with buf st-1

        load_stage(st + 3);

        const int buf = st & 3;
        uint4 ab[2], as_[2];
        float2 bbv[4], bsv[4];
#pragma unroll
        for (int i = 0; i < 2; ++i) {
            int mtl = mwarp * 2 + i;
            ab[i]  = *(const uint4*)&sA[buf][0][mtl * 32 + lane];
            as_[i] = *(const uint4*)&sA[buf][1][mtl * 32 + lane];
        }
#pragma unroll
        for (int j = 0; j < 4; ++j) {
            int ntl = nwarp * 4 + j;
            bbv[j] = sB[buf][0][ntl * 32 + lane];
            bsv[j] = sB[buf][1][ntl * 32 + lane];
        }
#pragma unroll
        for (int i = 0; i < 2; ++i)
#pragma unroll
            for (int j = 0; j < 4; ++j) {
                mma_tf32(acc[i][j], ab[i], bbv[j]);    // big*big
                mma_tf32(acc[i][j], ab[i], bsv[j]);    // big*small
                mma_tf32(acc[i][j], as_[i], bbv[j]);   // small*big
            }
    }

    // epilogue
    float* __restrict__ part = g_part[z];
    const int g = lane >> 2;
    const int c2 = (lane & 3) * 2;
#pragma unroll
    for (int i = 0; i < 2; ++i) {
#pragma unroll
        for (int j = 0; j < 4; ++j) {
            int m0 = (mb4 + mwarp * 2 + i) * 16 + g;
            int n0 = (nb8 + nwarp * 4 + j) * 8 + c2;
            *(float2*)&part[(size_t)m0 * GN + n0] = make_float2(acc[i][j].x, acc[i][j].y);
            *(float2*)&part[(size_t)(m0 + 8) * GN + n0] = make_float2(acc[i][j].z, acc[i][j].w);
        }
    }
}

// ---------------------------------------------------------------------------
// Combine split-K partials + bias. 600 blocks x 128 thr, 1 float4 each.
// ---------------------------------------------------------------------------
__global__ __launch_bounds__(128) void combine_kernel(const float* __restrict__ b2,
                                                      float* __restrict__ out) {
    int i = blockIdx.x * 128 + threadIdx.x;       // over GM*GN/4 = 76800
    float4 r = ((const float4*)b2)[i % (GN / 4)];
#pragma unroll
    for (int z = 0; z < SPLITK; ++z) {
        float4 p = ((const float4*)g_part[z])[i];
        r.x += p.x; r.y += p.y; r.z += p.z; r.w += p.w;
    }
    ((float4*)out)[i] = r;
}

// ---------------------------------------------------------------------------
extern "C" void kernel_launch(void* const* d_in, const int* in_sizes, int n_in,
                              void* d_out, int out_size) {
    const float* wf  = (const float*)d_in[0];   // [4,8192,768] f32
    const int*   ids = (const int*)d_in[1];     // [4,8192] i32
    const float* W2  = (const float*)d_in[2];   // [768,768] f32
    const float* b2  = (const float*)d_in[3];   // [768] f32
    float* out = (float*)d_out;                 // [4,100,768] f32

    init_kernel<<<384, 256>>>(ids);
    pool_kernel<<<POOL_BLOCKS, PBLK>>>(wf, ids);
    convert_kernel<<<(A_POS + B_POS + 255) / 256, 256>>>(W2);
    gemm_kernel<<<dim3(7, GN / 64, SPLITK), GEMM_THREADS>>>();
    combine_kernel<<<600, 128>>>(b2, out);
}

// round 10
// speedup vs baseline: 1.1855x; 1.1855x over previous
#include <cuda_runtime.h>
#include <cuda_bf16.h>
#include <math_constants.h>
#include <cstdint>

// Problem constants
#define BB 4
#define LL 8192
#define DD 768
#define MAXS 100
#define GM (BB*MAXS)   // 400
#define M2 512         // padded M storage (rows 400-511 zero)
#define GN DD          // 768
#define GK DD          // 768
#define NK16 (GK/16)   // 48
#define MTC 28         // computed m-tiles (448 rows >= 400)
#define NT (GN/8)      // 96 n-tiles

// pool config
#define TCH 32
#define PBLK 192
#define POOL_BLOCKS ((LL/TCH)*BB)        // 1024

// convert sizes
#define A16 (NK16 * MTC * 32)   // 43008
#define B16 (NK16 * NT * 32)    // 147456
#define CVB_BLOCKS (B16 / PBLK) // 768

// gemm config
#define SPLITK 6
#define K16_PER_Z (NK16/SPLITK) // 8 stages per block
#define GEMM_THREADS 128

// Scratch (device globals; allocation is forbidden)
__device__ float g_pooled[M2 * GK];        // [512][768] pooled, m-major
__device__ uint4 g_afb[A16];               // A frags big   [k16][mt][t]
__device__ uint4 g_afs[A16];               // A frags small
__device__ uint2 g_bfb[B16];               // B frags big   [k16][nt][t]
__device__ uint2 g_bfs[B16];               // B frags small
__device__ float g_part[SPLITK][M2 * GN];  // split-K partials

// ---------------------------------------------------------------------------
// helpers
// ---------------------------------------------------------------------------
__device__ __forceinline__ void atomMaxF(float* a, float v) {
    if (v >= 0.0f) atomicMax((int*)a, __float_as_int(v));
    else           atomicMin((unsigned int*)a, __float_as_uint(v));
}
__device__ __forceinline__ void cp_async16(unsigned int smem, const void* gmem) {
    asm volatile("cp.async.cg.shared.global [%0], [%1], 16;\n" :: "r"(smem), "l"(gmem));
}
__device__ __forceinline__ void cp_commit() {
    asm volatile("cp.async.commit_group;\n");
}
template <int N>
__device__ __forceinline__ void cp_wait() {
    asm volatile("cp.async.wait_group %0;\n" :: "n"(N));
}
// split x into bf16 big + bf16 small (guard inf so small never NaN)
__device__ __forceinline__ void bsplit(float x, __nv_bfloat16& b, __nv_bfloat16& s) {
    b = __float2bfloat16(x);
    float r = isinf(x) ? 0.0f : x - __bfloat162float(b);
    s = __float2bfloat16(r);
}
__device__ __forceinline__ unsigned packb(__nv_bfloat16 lo, __nv_bfloat16 hi) {
    __nv_bfloat162 v; v.x = lo; v.y = hi;
    return *reinterpret_cast<unsigned*>(&v);
}
__device__ __forceinline__ void mma_bf16(float4& d, uint4 a, uint2 b) {
    asm("mma.sync.aligned.m16n8k16.row.col.f32.bf16.bf16.f32 "
        "{%0,%1,%2,%3}, {%4,%5,%6,%7}, {%8,%9}, {%0,%1,%2,%3};"
        : "+f"(d.x), "+f"(d.y), "+f"(d.z), "+f"(d.w)
        : "r"(a.x), "r"(a.y), "r"(a.z), "r"(a.w), "r"(b.x), "r"(b.y));
}

// ---------------------------------------------------------------------------
// Init: g_pooled rows <400: -inf on valid slots else 0; rows 400-511: 0.
// ---------------------------------------------------------------------------
__global__ __launch_bounds__(256) void init_kernel(const int* __restrict__ ids) {
    int i4 = blockIdx.x * 256 + threadIdx.x;       // 0..98303
    int m = (i4 * 4) / DD;
    float val = 0.0f;
    if (m < GM) {
        int b = m / MAXS;
        int s = m - b * MAXS;
        int bbmax = __ldg(&ids[b * LL + LL - 1]);
        val = (s < bbmax) ? -CUDART_INF_F : 0.0f;
    }
    ((float4*)g_pooled)[i4] = make_float4(val, val, val, val);
}

// ---------------------------------------------------------------------------
// Pool + convert-B fused (independent jobs, overlap in one launch).
// Blocks [0, CVB_BLOCKS): W2 -> bf16 big/small fragments (m16n8k16 B layout:
//   lane t: g=t/4 (n), c=(t%4)*2 (k); b0=(k0,k0+1), b1=(k0+8,k0+9), k0=k16*16+c)
// Blocks [CVB_BLOCKS, +POOL_BLOCKS): token-parallel segment max.
// ---------------------------------------------------------------------------
__global__ __launch_bounds__(PBLK) void pool_kernel(const float* __restrict__ wf,
                                                    const int* __restrict__ ids,
                                                    const float* __restrict__ W2) {
    __shared__ int sid[TCH];
    const int tid = threadIdx.x;

    if (blockIdx.x < CVB_BLOCKS) {
        int j = blockIdx.x * PBLK + tid;           // 0..B16-1
        int t  = j & 31;
        int nt = (j >> 5) % NT;
        int k16 = j / (NT * 32);
        int g = t >> 2, c = (t & 3) * 2;
        int n  = nt * 8 + g;
        int k0 = k16 * 16 + c;
        const float* __restrict__ row = W2 + (size_t)n * GK;
        __nv_bfloat16 b00, s00, b01, s01, b10, s10, b11, s11;
        bsplit(row[k0],     b00, s00);
        bsplit(row[k0 + 1], b01, s01);
        bsplit(row[k0 + 8], b10, s10);
        bsplit(row[k0 + 9], b11, s11);
        g_bfb[j] = make_uint2(packb(b00, b01), packb(b10, b11));
        g_bfs[j] = make_uint2(packb(s00, s01), packb(s10, s11));
        return;
    }

    const int pb = blockIdx.x - CVB_BLOCKS;
    const int b = pb >> 8;                   // 256 chunks per batch
    const int c0 = (pb & 255) * TCH;
    if (tid < TCH) sid[tid] = ids[b * LL + c0 + tid];
    __syncthreads();

    const float4* __restrict__ base =
        (const float4*)(wf + ((size_t)b * LL + c0) * DD) + tid;

    float4 run = make_float4(-CUDART_INF_F, -CUDART_INF_F, -CUDART_INF_F, -CUDART_INF_F);
    int cur = -1;
    const int d0 = tid * 4;

#pragma unroll
    for (int t0 = 0; t0 < TCH; t0 += 8) {
        float4 v[8];
#pragma unroll
        for (int j = 0; j < 8; ++j)
            v[j] = __ldcs(base + (size_t)(t0 + j) * (DD / 4));
#pragma unroll
        for (int j = 0; j < 8; ++j) {
            int id = sid[t0 + j];
            if (id != cur) {
                if (cur > 0) {
                    float* p = g_pooled + (size_t)(b * MAXS + cur - 1) * DD + d0;
                    atomMaxF(p + 0, run.x);
                    atomMaxF(p + 1, run.y);
                    atomMaxF(p + 2, run.z);
                    atomMaxF(p + 3, run.w);
                }
                cur = id;
                run = make_float4(-CUDART_INF_F, -CUDART_INF_F, -CUDART_INF_F, -CUDART_INF_F);
            }
            if (id > 0) {
                run.x = fmaxf(run.x, v[j].x);
                run.y = fmaxf(run.y, v[j].y);
                run.z = fmaxf(run.z, v[j].z);
                run.w = fmaxf(run.w, v[j].w);
            }
        }
    }
    if (cur > 0) {
        float* p = g_pooled + (size_t)(b * MAXS + cur - 1) * DD + d0;
        atomMaxF(p + 0, run.x);
        atomMaxF(p + 1, run.y);
        atomMaxF(p + 2, run.z);
        atomMaxF(p + 3, run.w);
    }
}

// ---------------------------------------------------------------------------
// Convert-A: pooled -> bf16 big/small fragments (m16n8k16 A layout:
// lane t: g=t/4 (m), c=(t%4)*2 (k); a0=(r0,k0..k0+1) a1=(r1,k0..) a2=(r0,k0+8..)
// a3=(r1,k0+8..); r0=mt*16+g, r1=r0+8, k0=k16*16+c). 168 blocks x 256.
// ---------------------------------------------------------------------------
__global__ __launch_bounds__(256) void convertA_kernel() {
    int i = blockIdx.x * 256 + threadIdx.x;
    if (i >= A16) return;
    int t  = i & 31;
    int rest = i >> 5;
    int mt = rest % MTC;
    int k16 = rest / MTC;
    int g = t >> 2, c = (t & 3) * 2;
    int r0 = mt * 16 + g, r1 = r0 + 8;
    int k0 = k16 * 16 + c;
    const float* __restrict__ row0 = g_pooled + (size_t)r0 * GK;
    const float* __restrict__ row1 = g_pooled + (size_t)r1 * GK;
    __nv_bfloat16 bb[8], ss[8];
    bsplit(row0[k0],     bb[0], ss[0]);
    bsplit(row0[k0 + 1], bb[1], ss[1]);
    bsplit(row1[k0],     bb[2], ss[2]);
    bsplit(row1[k0 + 1], bb[3], ss[3]);
    bsplit(row0[k0 + 8], bb[4], ss[4]);
    bsplit(row0[k0 + 9], bb[5], ss[5]);
    bsplit(row1[k0 + 8], bb[6], ss[6]);
    bsplit(row1[k0 + 9], bb[7], ss[7]);
    int idx = (k16 * MTC + mt) * 32 + t;
    g_afb[idx] = make_uint4(packb(bb[0], bb[1]), packb(bb[2], bb[3]),
                            packb(bb[4], bb[5]), packb(bb[6], bb[7]));
    g_afs[idx] = make_uint4(packb(ss[0], ss[1]), packb(ss[2], ss[3]),
                            packb(ss[4], ss[5]), packb(ss[6], ss[7]));
}

// ---------------------------------------------------------------------------
// GEMM (3xBF16 m16n8k16): grid (7, 12, 6) = 504 blocks, 128 thr = 4 warps.
// Block tile 64m x 64n; warp tile 32m x 32n (2 mt x 4 nt).
// 4-deep cp.async pipeline, wait_group<2>, one barrier per k16 stage.
// ---------------------------------------------------------------------------
__global__ __launch_bounds__(GEMM_THREADS) void gemm_kernel() {
    __shared__ uint4 sA[4][2][128];   // [buf][big/sm][mt_local*32+t] 16KB
    __shared__ uint2 sB[4][2][256];   // [buf][big/sm][nt_local*32+t] 16KB

    const int mb4 = blockIdx.x * 4;        // mtile base (0..24)
    const int nb8 = blockIdx.y * 8;        // ntile base
    const int z = blockIdx.z;
    const int k16z = z * K16_PER_Z;

    const int tid = threadIdx.x;
    const int lane = tid & 31;
    const int wid = tid >> 5;
    const int mwarp = wid >> 1;            // 0..1
    const int nwarp = wid & 1;             // 0..1

    auto load_stage = [&](int st) {
        if (st < K16_PER_Z) {
            const int buf = st & 3;
            const int k16g = k16z + st;
            const uint4* srcAb = g_afb + ((size_t)k16g * MTC + mb4) * 32;
            const uint4* srcAs = g_afs + ((size_t)k16g * MTC + mb4) * 32;
            const uint4* srcBb = (const uint4*)(g_bfb + ((size_t)k16g * NT + nb8) * 32);
            const uint4* srcBs = (const uint4*)(g_bfs + ((size_t)k16g * NT + nb8) * 32);
            cp_async16((unsigned int)__cvta_generic_to_shared(&sA[buf][0][tid]), srcAb + tid);
            cp_async16((unsigned int)__cvta_generic_to_shared(&sA[buf][1][tid]), srcAs + tid);
            cp_async16((unsigned int)__cvta_generic_to_shared(&sB[buf][0][2 * tid]), srcBb + tid);
            cp_async16((unsigned int)__cvta_generic_to_shared(&sB[buf][1][2 * tid]), srcBs + tid);
        }
        cp_commit();   // empty commit past the end keeps wait<2> bookkeeping exact
    };

    float4 acc[2][4];
#pragma unroll
    for (int i = 0; i < 2; ++i)
#pragma unroll
        for (int j = 0; j < 4; ++j) acc[i][j] = make_float4(0.f, 0.f, 0.f, 0.f);

    load_stage(0);
    load_stage(1);
    load_stage(2);

    for (int st = 0; st < K16_PER_Z; ++st) {
        cp_wait<2>();
        __syncthreads();        // stage st resident; all warps done with buf st-1

        load_stage(st + 3);

        const int buf = st & 3;
        uint4 ab[2], as_[2];
        uint2 bbv[4], bsv[4];
#pragma unroll
        for (int i = 0; i < 2; ++i) {
            int mtl = mwarp * 2 + i;
            ab[i]  = sA[buf][0][mtl * 32 + lane];
            as_[i] = sA[buf][1][mtl * 32 + lane];
        }
#pragma unroll
        for (int j = 0; j < 4; ++j) {
            int ntl = nwarp * 4 + j;
            bbv[j] = sB[buf][0][ntl * 32 + lane];
            bsv[j] = sB[buf][1][ntl * 32 + lane];
        }
#pragma unroll
        for (int i = 0; i < 2; ++i)
#pragma unroll
            for (int j = 0; j < 4; ++j) {
                mma_bf16(acc[i][j], ab[i], bbv[j]);    // big*big
                mma_bf16(acc[i][j], ab[i], bsv[j]);    // big*small
                mma_bf16(acc[i][j], as_[i], bbv[j]);   // small*big
            }
    }

    // epilogue
    float* __restrict__ part = g_part[z];
    const int g = lane >> 2;
    const int c2 = (lane & 3) * 2;
#pragma unroll
    for (int i = 0; i < 2; ++i) {
#pragma unroll
        for (int j = 0; j < 4; ++j) {
            int m0 = (mb4 + mwarp * 2 + i) * 16 + g;
            int n0 = (nb8 + nwarp * 4 + j) * 8 + c2;
            *(float2*)&part[(size_t)m0 * GN + n0] = make_float2(acc[i][j].x, acc[i][j].y);
            *(float2*)&part[(size_t)(m0 + 8) * GN + n0] = make_float2(acc[i][j].z, acc[i][j].w);
        }
    }
}

// ---------------------------------------------------------------------------
// Combine split-K partials + bias. 600 blocks x 128 thr, 1 float4 each.
// ---------------------------------------------------------------------------
__global__ __launch_bounds__(128) void combine_kernel(const float* __restrict__ b2,
                                                      float* __restrict__ out) {
    int i = blockIdx.x * 128 + threadIdx.x;       // over GM*GN/4 = 76800
    float4 r = ((const float4*)b2)[i % (GN / 4)];
#pragma unroll
    for (int z = 0; z < SPLITK; ++z) {
        float4 p = ((const float4*)g_part[z])[i];
        r.x += p.x; r.y += p.y; r.z += p.z; r.w += p.w;
    }
    ((float4*)out)[i] = r;
}

// ---------------------------------------------------------------------------
extern "C" void kernel_launch(void* const* d_in, const int* in_sizes, int n_in,
                              void* d_out, int out_size) {
    const float* wf  = (const float*)d_in[0];   // [4,8192,768] f32
    const int*   ids = (const int*)d_in[1];     // [4,8192] i32
    const float* W2  = (const float*)d_in[2];   // [768,768] f32
    const float* b2  = (const float*)d_in[3];   // [768] f32
    float* out = (float*)d_out;                 // [4,100,768] f32

    init_kernel<<<384, 256>>>(ids);
    pool_kernel<<<CVB_BLOCKS + POOL_BLOCKS, PBLK>>>(wf, ids, W2);
    convertA_kernel<<<(A16 + 255) / 256, 256>>>();
    gemm_kernel<<<dim3(7, GN / 64, SPLITK), GEMM_THREADS>>>();
    combine_kernel<<<600, 128>>>(b2, out);
}